// round 10
// baseline (speedup 1.0000x reference)
#include <cuda_runtime.h>
#include <cuda_bf16.h>

#define NN 4
#define CC 256
#define HWX 4096
#define NH 4
#define DH 64
#define CNT (CC*HWX)

// Scratch (device globals: allocation-free rule)
// Q,K: [n][part][h][p][d] (d contig). V: [n][2][h][d][p] (p contig).
__device__ __nv_bfloat16 g_qkv[(size_t)NN * 3 * NH * HWX * DH];  // ~25 MB
__device__ __nv_bfloat16 g_y  [(size_t)NN * NH * HWX * DH];      // ~8 MB, [n][h][p][d]
__device__ float g_part[NN * 64 * 2];
__device__ float g_stats[NN * 2];

// ---------------------------------------------------------------------------
// helpers
// ---------------------------------------------------------------------------
__device__ __forceinline__ unsigned pack_bf16(float lo, float hi) {
    unsigned r;
    asm("cvt.rn.bf16x2.f32 %0, %1, %2;" : "=r"(r) : "f"(hi), "f"(lo));
    return r;
}

__device__ __forceinline__ float ex2(float x) {
    float r;
    asm("ex2.approx.f32 %0, %1;" : "=f"(r) : "f"(x));
    return r;
}

__device__ __forceinline__ void mma_bf16(float* d, const unsigned* a,
                                         unsigned b0, unsigned b1) {
    asm("mma.sync.aligned.m16n8k16.row.col.f32.bf16.bf16.f32 "
        "{%0,%1,%2,%3}, {%4,%5,%6,%7}, {%8,%9}, {%0,%1,%2,%3};"
        : "+f"(d[0]), "+f"(d[1]), "+f"(d[2]), "+f"(d[3])
        : "r"(a[0]), "r"(a[1]), "r"(a[2]), "r"(a[3]), "r"(b0), "r"(b1));
}

// ldmatrix x4: 4 8x8 b16 matrices; lane L supplies row (L&7) of matrix (L>>3).
__device__ __forceinline__ void ldsm4(unsigned& r0, unsigned& r1,
                                      unsigned& r2, unsigned& r3, const void* p) {
    unsigned a = (unsigned)__cvta_generic_to_shared(p);
    asm volatile("ldmatrix.sync.aligned.m8n8.x4.shared.b16 {%0,%1,%2,%3}, [%4];"
        : "=r"(r0), "=r"(r1), "=r"(r2), "=r"(r3) : "r"(a));
}

__device__ __forceinline__ void cp16(void* smem, const void* g) {
    unsigned s = (unsigned)__cvta_generic_to_shared(smem);
    asm volatile("cp.async.cg.shared.global [%0], [%1], 16;" :: "r"(s), "l"(g));
}
#define CP_COMMIT() asm volatile("cp.async.commit_group;")
#define CP_WAIT0()  asm volatile("cp.async.wait_group 0;")

// ---------------------------------------------------------------------------
// GroupNorm(1, C): two-pass deterministic reduction
// ---------------------------------------------------------------------------
__global__ void gn_partial_k(const float* __restrict__ x) {
    int n = blockIdx.y, b = blockIdx.x, tid = threadIdx.x;
    const float4* px = (const float4*)(x + (size_t)n * CNT + (size_t)b * 16384);
    float s = 0.f, s2 = 0.f;
#pragma unroll
    for (int i = 0; i < 16; ++i) {
        float4 v = px[tid + i * 256];
        s  += v.x + v.y + v.z + v.w;
        s2 += v.x*v.x + v.y*v.y + v.z*v.z + v.w*v.w;
    }
    __shared__ float rs[256], rq[256];
    rs[tid] = s; rq[tid] = s2;
    __syncthreads();
    for (int off = 128; off > 0; off >>= 1) {
        if (tid < off) { rs[tid] += rs[tid + off]; rq[tid] += rq[tid + off]; }
        __syncthreads();
    }
    if (tid == 0) {
        g_part[(n * 64 + b) * 2 + 0] = rs[0];
        g_part[(n * 64 + b) * 2 + 1] = rq[0];
    }
}

__global__ void gn_final_k() {
    int n = blockIdx.x, t = threadIdx.x;
    __shared__ float rs[64], rq[64];
    rs[t] = g_part[(n * 64 + t) * 2 + 0];
    rq[t] = g_part[(n * 64 + t) * 2 + 1];
    __syncthreads();
    for (int off = 32; off > 0; off >>= 1) {
        if (t < off) { rs[t] += rs[t + off]; rq[t] += rq[t + off]; }
        __syncthreads();
    }
    if (t == 0) {
        float mean = rs[0] / (float)CNT;
        float var  = rq[0] / (float)CNT - mean * mean;
        g_stats[n * 2 + 0] = mean;
        g_stats[n * 2 + 1] = rsqrtf(var + 1e-5f);
    }
}

// ---------------------------------------------------------------------------
// QKV projection: bf16 mma, fp32 accum. C[m=p][n=o] = sum_c xn[c,p] W[o,c].
// Tile 128p x 64o, K in 4 chunks of 64. ldmatrix for all fragments.
// ---------------------------------------------------------------------------
__global__ void __launch_bounds__(256) qkv_gemm_k(
        const float* __restrict__ x,
        const float* __restrict__ wqkv,
        const float* __restrict__ bqkv,
        const float* __restrict__ gamma,
        const float* __restrict__ beta) {
    int n = blockIdx.z;
    int p0 = blockIdx.x * 128, o0 = blockIdx.y * 64;
    int tid = threadIdx.x, w = tid >> 5, lane = tid & 31;
    int lr = lane >> 2, lc = lane & 3;
    int lmrow = lane & 7, lmmat = lane >> 3;  // ldmatrix addressing
    float mean = g_stats[n * 2], rstd = g_stats[n * 2 + 1];

    __shared__ __nv_bfloat16 Xs[128][72];  // [p][c]
    __shared__ __nv_bfloat16 Ws[64][72];   // [o][c]

    float acc[8][4];
#pragma unroll
    for (int i = 0; i < 8; ++i)
#pragma unroll
        for (int j = 0; j < 4; ++j) acc[i][j] = 0.f;

    const float* xb = x + (size_t)n * CNT;
    int wrow = tid >> 2, wq = tid & 3;
    int c_l = tid >> 2, pq = tid & 3;

    for (int ch = 0; ch < 4; ++ch) {
        int c0 = ch * 64;
#pragma unroll
        for (int i = 0; i < 4; ++i) {
            int cc = wq * 16 + i * 4;
            float4 wv = *(const float4*)&wqkv[(o0 + wrow) * CC + c0 + cc];
            Ws[wrow][cc+0] = __float2bfloat16(wv.x);
            Ws[wrow][cc+1] = __float2bfloat16(wv.y);
            Ws[wrow][cc+2] = __float2bfloat16(wv.z);
            Ws[wrow][cc+3] = __float2bfloat16(wv.w);
        }
        {
            int c = c0 + c_l;
            float ga = gamma[c] * rstd;
            float be = beta[c] - mean * rstd * gamma[c];
            const float* xr = &xb[(size_t)c * HWX + p0];
#pragma unroll
            for (int i = 0; i < 8; ++i) {
                int pl = pq * 32 + i * 4;
                float4 xv = *(const float4*)&xr[pl];
                Xs[pl+0][c_l] = __float2bfloat16(xv.x * ga + be);
                Xs[pl+1][c_l] = __float2bfloat16(xv.y * ga + be);
                Xs[pl+2][c_l] = __float2bfloat16(xv.z * ga + be);
                Xs[pl+3][c_l] = __float2bfloat16(xv.w * ga + be);
            }
        }
        __syncthreads();
#pragma unroll
        for (int s = 0; s < 4; ++s) {
            int col = s * 16;
            unsigned a[4];
            ldsm4(a[0], a[1], a[2], a[3],
                  &Xs[w * 16 + (lmmat & 1) * 8 + lmrow][col + (lmmat >> 1) * 8]);
#pragma unroll
            for (int np = 0; np < 4; ++np) {
                unsigned b00, b01, b10, b11;
                ldsm4(b00, b01, b10, b11,
                      &Ws[(np * 2 + (lmmat >> 1)) * 8 + lmrow][col + (lmmat & 1) * 8]);
                mma_bf16(acc[np * 2],     a, b00, b01);
                mma_bf16(acc[np * 2 + 1], a, b10, b11);
            }
        }
        __syncthreads();
    }

    int part = o0 >> 8, hh = (o0 >> 6) & 3;
    __nv_bfloat16* hb = g_qkv + (((size_t)n * 3 + part) * NH + hh) * (size_t)HWX * DH;
    int p_r = p0 + w * 16 + lr;
#pragma unroll
    for (int nt = 0; nt < 8; ++nt) {
        int d = nt * 8 + lc * 2;
        float b0 = bqkv[o0 + d], b1 = bqkv[o0 + d + 1];
        if (part < 2) {
            *(unsigned*)&hb[(size_t)p_r * DH + d] =
                pack_bf16(acc[nt][0] + b0, acc[nt][1] + b1);
            *(unsigned*)&hb[(size_t)(p_r + 8) * DH + d] =
                pack_bf16(acc[nt][2] + b0, acc[nt][3] + b1);
        } else {  // V: [d][p]
            hb[(size_t)d * HWX + p_r]           = __float2bfloat16(acc[nt][0] + b0);
            hb[(size_t)(d + 1) * HWX + p_r]     = __float2bfloat16(acc[nt][1] + b1);
            hb[(size_t)d * HWX + p_r + 8]       = __float2bfloat16(acc[nt][2] + b0);
            hb[(size_t)(d + 1) * HWX + p_r + 8] = __float2bfloat16(acc[nt][3] + b1);
        }
    }
}

// ---------------------------------------------------------------------------
// Flash attention, bf16 mma + ldmatrix + cp.async double buffering.
// S phase restructured np-outer so ex2/pack of one n-tile pair overlaps the
// next pair's mmas (kills the serial softmax bubble); sacc never materializes
// as a 32-reg array -> lower register pressure.
// ---------------------------------------------------------------------------
__global__ void __launch_bounds__(256) attn_k() {
    int qt = blockIdx.x, hh = blockIdx.y, n = blockIdx.z;
    int tid = threadIdx.x, w = tid >> 5, lane = tid & 31;
    int lr = lane >> 2, lc = lane & 3;
    int lmrow = lane & 7, lmmat = lane >> 3;

    __shared__ __nv_bfloat16 Ks[2][64][72];  // [c][d]
    __shared__ __nv_bfloat16 Vt[2][64][72];  // [d][c]

    const __nv_bfloat16* Q = g_qkv + (((size_t)n * 3 + 0) * NH + hh) * (size_t)HWX * DH;
    const __nv_bfloat16* K = g_qkv + (((size_t)n * 3 + 1) * NH + hh) * (size_t)HWX * DH;
    const __nv_bfloat16* V = g_qkv + (((size_t)n * 3 + 2) * NH + hh) * (size_t)HWX * DH;

    // Q frags, pre-scaled by 0.125*log2(e) so S is in log2 domain.
    const float QSC = 0.18033688011112042f;
    unsigned qf[4][4];
    int r0 = qt * 128 + w * 16 + lr;
#pragma unroll
    for (int s = 0; s < 4; ++s) {
        int c0 = s * 16 + lc * 2;
        const size_t rA = (size_t)r0 * DH, rB = (size_t)(r0 + 8) * DH;
        unsigned raw[4] = {
            *(const unsigned*)&Q[rA + c0], *(const unsigned*)&Q[rB + c0],
            *(const unsigned*)&Q[rA + c0 + 8], *(const unsigned*)&Q[rB + c0 + 8] };
#pragma unroll
        for (int i = 0; i < 4; ++i) {
            float2 f = __bfloat1622float2(*(__nv_bfloat162*)&raw[i]);
            qf[s][i] = pack_bf16(f.x * QSC, f.y * QSC);
        }
    }

    float oacc[8][4];
#pragma unroll
    for (int i = 0; i < 8; ++i)
#pragma unroll
        for (int j = 0; j < 4; ++j) oacc[i][j] = 0.f;
    float lsum0 = 0.f, lsum1 = 0.f;

    int srow = tid >> 2, scol = (tid & 3) * 16;

    cp16(&Ks[0][srow][scol],     &K[((size_t)srow) * DH + scol]);
    cp16(&Ks[0][srow][scol + 8], &K[((size_t)srow) * DH + scol + 8]);
    cp16(&Vt[0][srow][scol],     &V[(size_t)srow * HWX + scol]);
    cp16(&Vt[0][srow][scol + 8], &V[(size_t)srow * HWX + scol + 8]);
    CP_COMMIT();

    for (int kt = 0; kt < 64; ++kt) {
        int buf = kt & 1;
        CP_WAIT0();
        __syncthreads();
        if (kt < 63) {
            int nx = kt + 1, nb = buf ^ 1;
            cp16(&Ks[nb][srow][scol],     &K[((size_t)(nx * 64 + srow)) * DH + scol]);
            cp16(&Ks[nb][srow][scol + 8], &K[((size_t)(nx * 64 + srow)) * DH + scol + 8]);
            cp16(&Vt[nb][srow][scol],     &V[(size_t)srow * HWX + nx * 64 + scol]);
            cp16(&Vt[nb][srow][scol + 8], &V[(size_t)srow * HWX + nx * 64 + scol + 8]);
            CP_COMMIT();
        }

        // S = Q K^T, np-outer: each n-tile pair's mma chain completes, then its
        // exps issue while the next pair's mmas run (MUFU overlaps tensor).
        unsigned pa[4][4];
#pragma unroll
        for (int np = 0; np < 4; ++np) {
            float s0[4] = {0.f, 0.f, 0.f, 0.f};
            float s1[4] = {0.f, 0.f, 0.f, 0.f};
#pragma unroll
            for (int s = 0; s < 4; ++s) {
                int col = s * 16;
                unsigned b00, b01, b10, b11;
                ldsm4(b00, b01, b10, b11,
                      &Ks[buf][(np * 2 + (lmmat >> 1)) * 8 + lmrow][col + (lmmat & 1) * 8]);
                mma_bf16(s0, qf[s], b00, b01);
                mma_bf16(s1, qf[s], b10, b11);
            }
            // P = 2^S for n-tiles 2np (s0) and 2np+1 (s1); pack into PV a-frags.
            float e0 = ex2(s0[0]), e1 = ex2(s0[1]), e2 = ex2(s0[2]), e3 = ex2(s0[3]);
            float f0 = ex2(s1[0]), f1 = ex2(s1[1]), f2 = ex2(s1[2]), f3 = ex2(s1[3]);
            lsum0 += (e0 + e1) + (f0 + f1);
            lsum1 += (e2 + e3) + (f2 + f3);
            pa[np][0] = pack_bf16(e0, e1);
            pa[np][1] = pack_bf16(e2, e3);
            pa[np][2] = pack_bf16(f0, f1);
            pa[np][3] = pack_bf16(f2, f3);
        }

        // O += P V
#pragma unroll
        for (int s = 0; s < 4; ++s) {
            int col = s * 16;
#pragma unroll
            for (int np = 0; np < 4; ++np) {
                unsigned b00, b01, b10, b11;
                ldsm4(b00, b01, b10, b11,
                      &Vt[buf][(np * 2 + (lmmat >> 1)) * 8 + lmrow][col + (lmmat & 1) * 8]);
                mma_bf16(oacc[np * 2],     pa[s], b00, b01);
                mma_bf16(oacc[np * 2 + 1], pa[s], b10, b11);
            }
        }
    }

    lsum0 += __shfl_xor_sync(0xffffffffu, lsum0, 1);
    lsum0 += __shfl_xor_sync(0xffffffffu, lsum0, 2);
    lsum1 += __shfl_xor_sync(0xffffffffu, lsum1, 1);
    lsum1 += __shfl_xor_sync(0xffffffffu, lsum1, 2);
    float inv0 = 1.f / lsum0, inv1 = 1.f / lsum1;

    __nv_bfloat16* Y = g_y + ((size_t)n * NH + hh) * (size_t)HWX * DH;
#pragma unroll
    for (int nt = 0; nt < 8; ++nt) {
        int d0 = nt * 8 + lc * 2;
        *(unsigned*)&Y[(size_t)r0 * DH + d0] =
            pack_bf16(oacc[nt][0] * inv0, oacc[nt][1] * inv0);
        *(unsigned*)&Y[(size_t)(r0 + 8) * DH + d0] =
            pack_bf16(oacc[nt][2] * inv1, oacc[nt][3] * inv1);
    }
}

// ---------------------------------------------------------------------------
// Output projection: bf16 mma + ldmatrix. C[m=o][n=p] = sum_c Wout[o,c] y[c,p].
// ---------------------------------------------------------------------------
__global__ void __launch_bounds__(256) outproj_k(
        const float* __restrict__ x,
        const float* __restrict__ wout,
        const float* __restrict__ bout,
        float* __restrict__ out) {
    int n = blockIdx.z;
    int p0 = blockIdx.x * 64, o0 = blockIdx.y * 128;
    int tid = threadIdx.x, w = tid >> 5, lane = tid & 31;
    int lr = lane >> 2, lc = lane & 3;
    int lmrow = lane & 7, lmmat = lane >> 3;

    __shared__ __nv_bfloat16 As[128][72];  // Wout [o][c]
    __shared__ __nv_bfloat16 Bs[64][72];   // Y [p][d] per head chunk

    float acc[8][4];
#pragma unroll
    for (int i = 0; i < 8; ++i)
#pragma unroll
        for (int j = 0; j < 4; ++j) acc[i][j] = 0.f;

    int ar = tid >> 1, ah = tid & 1;
    int br = tid >> 2, bq = tid & 3;

    for (int hh = 0; hh < 4; ++hh) {
        int c0 = hh * 64;
#pragma unroll
        for (int i = 0; i < 8; ++i) {
            int cc = ah * 32 + i * 4;
            float4 wv = *(const float4*)&wout[(o0 + ar) * CC + c0 + cc];
            As[ar][cc+0] = __float2bfloat16(wv.x);
            As[ar][cc+1] = __float2bfloat16(wv.y);
            As[ar][cc+2] = __float2bfloat16(wv.z);
            As[ar][cc+3] = __float2bfloat16(wv.w);
        }
        {
            const __nv_bfloat16* Yb = g_y + ((size_t)n * NH + hh) * (size_t)HWX * DH;
            const uint4* src = (const uint4*)&Yb[(size_t)(p0 + br) * DH + bq * 16];
            uint4 y0 = src[0], y1 = src[1];
            *(uint4*)&Bs[br][bq * 16]     = y0;
            *(uint4*)&Bs[br][bq * 16 + 8] = y1;
        }
        __syncthreads();
#pragma unroll
        for (int s = 0; s < 4; ++s) {
            int col = s * 16;
            unsigned a[4];
            ldsm4(a[0], a[1], a[2], a[3],
                  &As[w * 16 + (lmmat & 1) * 8 + lmrow][col + (lmmat >> 1) * 8]);
#pragma unroll
            for (int np = 0; np < 4; ++np) {
                unsigned b00, b01, b10, b11;
                ldsm4(b00, b01, b10, b11,
                      &Bs[(np * 2 + (lmmat >> 1)) * 8 + lmrow][col + (lmmat & 1) * 8]);
                mma_bf16(acc[np * 2],     a, b00, b01);
                mma_bf16(acc[np * 2 + 1], a, b10, b11);
            }
        }
        __syncthreads();
    }

    const float* xb = x + (size_t)n * CNT;
    float*       ob = out + (size_t)n * CNT;
    int o_r = o0 + w * 16 + lr;
    float biasA = bout[o_r], biasB = bout[o_r + 8];
#pragma unroll
    for (int nt = 0; nt < 8; ++nt) {
        int p = p0 + nt * 8 + lc * 2;
        float2 xrA = *(const float2*)&xb[(size_t)o_r * HWX + p];
        float2 xrB = *(const float2*)&xb[(size_t)(o_r + 8) * HWX + p];
        float2 rA = make_float2(acc[nt][0] + biasA + xrA.x,
                                acc[nt][1] + biasA + xrA.y);
        float2 rB = make_float2(acc[nt][2] + biasB + xrB.x,
                                acc[nt][3] + biasB + xrB.y);
        *(float2*)&ob[(size_t)o_r * HWX + p]       = rA;
        *(float2*)&ob[(size_t)(o_r + 8) * HWX + p] = rB;
    }
}

// ---------------------------------------------------------------------------
extern "C" void kernel_launch(void* const* d_in, const int* in_sizes, int n_in,
                              void* d_out, int out_size) {
    const float* x     = (const float*)d_in[0];
    const float* gamma = (const float*)d_in[1];
    const float* beta  = (const float*)d_in[2];
    const float* wqkv  = (const float*)d_in[3];
    const float* bqkv  = (const float*)d_in[4];
    const float* wout  = (const float*)d_in[5];
    const float* bout  = (const float*)d_in[6];
    float* out = (float*)d_out;

    gn_partial_k<<<dim3(64, NN), 256>>>(x);
    gn_final_k  <<<NN, 64>>>();
    qkv_gemm_k  <<<dim3(32, 12, NN), 256>>>(x, wqkv, bqkv, gamma, beta);
    attn_k      <<<dim3(32, NH, NN), 256>>>();
    outproj_k   <<<dim3(64, 2, NN), 256>>>(x, wout, bout, out);
}

// round 12
// speedup vs baseline: 1.0253x; 1.0253x over previous
#include <cuda_runtime.h>
#include <cuda_bf16.h>

#define NN 4
#define CC 256
#define HWX 4096
#define NH 4
#define DH 64
#define CNT (CC*HWX)

// Scratch (device globals: allocation-free rule)
// Q,K: [n][part][h][p][d] (d contig). V: [n][2][h][d][p] (p contig).
__device__ __nv_bfloat16 g_qkv[(size_t)NN * 3 * NH * HWX * DH];  // ~25 MB
__device__ __nv_bfloat16 g_y  [(size_t)NN * NH * HWX * DH];      // ~8 MB, [n][h][p][d]
__device__ float g_part[NN * 64 * 2];
__device__ float g_stats[NN * 2];

// ---------------------------------------------------------------------------
// helpers
// ---------------------------------------------------------------------------
__device__ __forceinline__ unsigned pack_bf16(float lo, float hi) {
    unsigned r;
    asm("cvt.rn.bf16x2.f32 %0, %1, %2;" : "=r"(r) : "f"(hi), "f"(lo));
    return r;
}

__device__ __forceinline__ float ex2(float x) {
    float r;
    asm("ex2.approx.f32 %0, %1;" : "=f"(r) : "f"(x));
    return r;
}

__device__ __forceinline__ void mma_bf16(float* d, const unsigned* a,
                                         unsigned b0, unsigned b1) {
    asm("mma.sync.aligned.m16n8k16.row.col.f32.bf16.bf16.f32 "
        "{%0,%1,%2,%3}, {%4,%5,%6,%7}, {%8,%9}, {%0,%1,%2,%3};"
        : "+f"(d[0]), "+f"(d[1]), "+f"(d[2]), "+f"(d[3])
        : "r"(a[0]), "r"(a[1]), "r"(a[2]), "r"(a[3]), "r"(b0), "r"(b1));
}

// ldmatrix x4: 4 8x8 b16 matrices; lane L supplies row (L&7) of matrix (L>>3).
__device__ __forceinline__ void ldsm4(unsigned& r0, unsigned& r1,
                                      unsigned& r2, unsigned& r3, const void* p) {
    unsigned a = (unsigned)__cvta_generic_to_shared(p);
    asm volatile("ldmatrix.sync.aligned.m8n8.x4.shared.b16 {%0,%1,%2,%3}, [%4];"
        : "=r"(r0), "=r"(r1), "=r"(r2), "=r"(r3) : "r"(a));
}

__device__ __forceinline__ void cp16(void* smem, const void* g) {
    unsigned s = (unsigned)__cvta_generic_to_shared(smem);
    asm volatile("cp.async.cg.shared.global [%0], [%1], 16;" :: "r"(s), "l"(g));
}
#define CP_COMMIT() asm volatile("cp.async.commit_group;")
#define CP_WAIT0()  asm volatile("cp.async.wait_group 0;")

// ---------------------------------------------------------------------------
// GroupNorm(1, C): two-pass deterministic reduction
// ---------------------------------------------------------------------------
__global__ void gn_partial_k(const float* __restrict__ x) {
    int n = blockIdx.y, b = blockIdx.x, tid = threadIdx.x;
    const float4* px = (const float4*)(x + (size_t)n * CNT + (size_t)b * 16384);
    float s = 0.f, s2 = 0.f;
#pragma unroll
    for (int i = 0; i < 16; ++i) {
        float4 v = px[tid + i * 256];
        s  += v.x + v.y + v.z + v.w;
        s2 += v.x*v.x + v.y*v.y + v.z*v.z + v.w*v.w;
    }
    __shared__ float rs[256], rq[256];
    rs[tid] = s; rq[tid] = s2;
    __syncthreads();
    for (int off = 128; off > 0; off >>= 1) {
        if (tid < off) { rs[tid] += rs[tid + off]; rq[tid] += rq[tid + off]; }
        __syncthreads();
    }
    if (tid == 0) {
        g_part[(n * 64 + b) * 2 + 0] = rs[0];
        g_part[(n * 64 + b) * 2 + 1] = rq[0];
    }
}

__global__ void gn_final_k() {
    int n = blockIdx.x, t = threadIdx.x;
    __shared__ float rs[64], rq[64];
    rs[t] = g_part[(n * 64 + t) * 2 + 0];
    rq[t] = g_part[(n * 64 + t) * 2 + 1];
    __syncthreads();
    for (int off = 32; off > 0; off >>= 1) {
        if (t < off) { rs[t] += rs[t + off]; rq[t] += rq[t + off]; }
        __syncthreads();
    }
    if (t == 0) {
        float mean = rs[0] / (float)CNT;
        float var  = rq[0] / (float)CNT - mean * mean;
        g_stats[n * 2 + 0] = mean;
        g_stats[n * 2 + 1] = rsqrtf(var + 1e-5f);
    }
}

// ---------------------------------------------------------------------------
// QKV projection: bf16 mma, fp32 accum. C[m=p][n=o] = sum_c xn[c,p] W[o,c].
// Tile 128p x 64o, K in 4 chunks of 64. ldmatrix for all fragments.
// ---------------------------------------------------------------------------
__global__ void __launch_bounds__(256) qkv_gemm_k(
        const float* __restrict__ x,
        const float* __restrict__ wqkv,
        const float* __restrict__ bqkv,
        const float* __restrict__ gamma,
        const float* __restrict__ beta) {
    int n = blockIdx.z;
    int p0 = blockIdx.x * 128, o0 = blockIdx.y * 64;
    int tid = threadIdx.x, w = tid >> 5, lane = tid & 31;
    int lr = lane >> 2, lc = lane & 3;
    int lmrow = lane & 7, lmmat = lane >> 3;  // ldmatrix addressing
    float mean = g_stats[n * 2], rstd = g_stats[n * 2 + 1];

    __shared__ __nv_bfloat16 Xs[128][72];  // [p][c]
    __shared__ __nv_bfloat16 Ws[64][72];   // [o][c]

    float acc[8][4];
#pragma unroll
    for (int i = 0; i < 8; ++i)
#pragma unroll
        for (int j = 0; j < 4; ++j) acc[i][j] = 0.f;

    const float* xb = x + (size_t)n * CNT;
    int wrow = tid >> 2, wq = tid & 3;
    int c_l = tid >> 2, pq = tid & 3;

    for (int ch = 0; ch < 4; ++ch) {
        int c0 = ch * 64;
#pragma unroll
        for (int i = 0; i < 4; ++i) {
            int cc = wq * 16 + i * 4;
            float4 wv = *(const float4*)&wqkv[(o0 + wrow) * CC + c0 + cc];
            Ws[wrow][cc+0] = __float2bfloat16(wv.x);
            Ws[wrow][cc+1] = __float2bfloat16(wv.y);
            Ws[wrow][cc+2] = __float2bfloat16(wv.z);
            Ws[wrow][cc+3] = __float2bfloat16(wv.w);
        }
        {
            int c = c0 + c_l;
            float ga = gamma[c] * rstd;
            float be = beta[c] - mean * rstd * gamma[c];
            const float* xr = &xb[(size_t)c * HWX + p0];
#pragma unroll
            for (int i = 0; i < 8; ++i) {
                int pl = pq * 32 + i * 4;
                float4 xv = *(const float4*)&xr[pl];
                Xs[pl+0][c_l] = __float2bfloat16(xv.x * ga + be);
                Xs[pl+1][c_l] = __float2bfloat16(xv.y * ga + be);
                Xs[pl+2][c_l] = __float2bfloat16(xv.z * ga + be);
                Xs[pl+3][c_l] = __float2bfloat16(xv.w * ga + be);
            }
        }
        __syncthreads();
#pragma unroll
        for (int s = 0; s < 4; ++s) {
            int col = s * 16;
            unsigned a[4];
            ldsm4(a[0], a[1], a[2], a[3],
                  &Xs[w * 16 + (lmmat & 1) * 8 + lmrow][col + (lmmat >> 1) * 8]);
#pragma unroll
            for (int np = 0; np < 4; ++np) {
                unsigned b00, b01, b10, b11;
                ldsm4(b00, b01, b10, b11,
                      &Ws[(np * 2 + (lmmat >> 1)) * 8 + lmrow][col + (lmmat & 1) * 8]);
                mma_bf16(acc[np * 2],     a, b00, b01);
                mma_bf16(acc[np * 2 + 1], a, b10, b11);
            }
        }
        __syncthreads();
    }

    int part = o0 >> 8, hh = (o0 >> 6) & 3;
    __nv_bfloat16* hb = g_qkv + (((size_t)n * 3 + part) * NH + hh) * (size_t)HWX * DH;
    int p_r = p0 + w * 16 + lr;
#pragma unroll
    for (int nt = 0; nt < 8; ++nt) {
        int d = nt * 8 + lc * 2;
        float b0 = bqkv[o0 + d], b1 = bqkv[o0 + d + 1];
        if (part < 2) {
            *(unsigned*)&hb[(size_t)p_r * DH + d] =
                pack_bf16(acc[nt][0] + b0, acc[nt][1] + b1);
            *(unsigned*)&hb[(size_t)(p_r + 8) * DH + d] =
                pack_bf16(acc[nt][2] + b0, acc[nt][3] + b1);
        } else {  // V: [d][p]
            hb[(size_t)d * HWX + p_r]           = __float2bfloat16(acc[nt][0] + b0);
            hb[(size_t)(d + 1) * HWX + p_r]     = __float2bfloat16(acc[nt][1] + b1);
            hb[(size_t)d * HWX + p_r + 8]       = __float2bfloat16(acc[nt][2] + b0);
            hb[(size_t)(d + 1) * HWX + p_r + 8] = __float2bfloat16(acc[nt][3] + b1);
        }
    }
}

// ---------------------------------------------------------------------------
// Flash attention, bf16 mma + ldmatrix + cp.async double buffering.
// Hand-pipelined volatile ldsm stream with a 3-slot rotating fragment buffer:
// load frag i+2 into slot (i+2)%3 while mma consumes slot i%3 (no WAR hazard,
// unlike a 2-slot ring). exp of score-tile c-1 issues during tile c's mmas.
// ---------------------------------------------------------------------------
__global__ void __launch_bounds__(256) attn_k() {
    int qt = blockIdx.x, hh = blockIdx.y, n = blockIdx.z;
    int tid = threadIdx.x, w = tid >> 5, lane = tid & 31;
    int lr = lane >> 2, lc = lane & 3;
    int lmrow = lane & 7, lmmat = lane >> 3;

    __shared__ __nv_bfloat16 Ks[2][64][72];  // [c][d]
    __shared__ __nv_bfloat16 Vt[2][64][72];  // [d][c]

    const __nv_bfloat16* Q = g_qkv + (((size_t)n * 3 + 0) * NH + hh) * (size_t)HWX * DH;
    const __nv_bfloat16* K = g_qkv + (((size_t)n * 3 + 1) * NH + hh) * (size_t)HWX * DH;
    const __nv_bfloat16* V = g_qkv + (((size_t)n * 3 + 2) * NH + hh) * (size_t)HWX * DH;

    // Q frags, pre-scaled by 0.125*log2(e) so S is in log2 domain.
    const float QSC = 0.18033688011112042f;
    unsigned qf[4][4];
    int r0 = qt * 128 + w * 16 + lr;
#pragma unroll
    for (int s = 0; s < 4; ++s) {
        int c0 = s * 16 + lc * 2;
        const size_t rA = (size_t)r0 * DH, rB = (size_t)(r0 + 8) * DH;
        unsigned raw[4] = {
            *(const unsigned*)&Q[rA + c0], *(const unsigned*)&Q[rB + c0],
            *(const unsigned*)&Q[rA + c0 + 8], *(const unsigned*)&Q[rB + c0 + 8] };
#pragma unroll
        for (int i = 0; i < 4; ++i) {
            float2 f = __bfloat1622float2(*(__nv_bfloat162*)&raw[i]);
            qf[s][i] = pack_bf16(f.x * QSC, f.y * QSC);
        }
    }

    float oacc[8][4];
#pragma unroll
    for (int i = 0; i < 8; ++i)
#pragma unroll
        for (int j = 0; j < 4; ++j) oacc[i][j] = 0.f;
    float lsum0 = 0.f, lsum1 = 0.f;

    int srow = tid >> 2, scol = (tid & 3) * 16;

    cp16(&Ks[0][srow][scol],     &K[((size_t)srow) * DH + scol]);
    cp16(&Ks[0][srow][scol + 8], &K[((size_t)srow) * DH + scol + 8]);
    cp16(&Vt[0][srow][scol],     &V[(size_t)srow * HWX + scol]);
    cp16(&Vt[0][srow][scol + 8], &V[(size_t)srow * HWX + scol + 8]);
    CP_COMMIT();

// K-frag load i into rotating slot i%3: score n-tile pair np=i>>2, k-step s=i&3
#define LDKF(i) ldsm4(kb[(i)%3][0], kb[(i)%3][1], kb[(i)%3][2], kb[(i)%3][3], \
    &Ks[buf][(((i) >> 2) * 2 + (lmmat >> 1)) * 8 + lmrow][((i) & 3) * 16 + (lmmat & 1) * 8])
// V-frag load i into rotating slot i%3: k-step s=i>>2, d n-tile pair np=i&3
#define LDVF(i) ldsm4(vb[(i)%3][0], vb[(i)%3][1], vb[(i)%3][2], vb[(i)%3][3], \
    &Vt[buf][(((i) & 3) * 2 + (lmmat >> 1)) * 8 + lmrow][((i) >> 2) * 16 + (lmmat & 1) * 8])
// exp+pack score tile pair c from parity slot sl
#define EXPPACK(c, sl) do { \
    float e0 = ex2(accS[sl][0][0]), e1 = ex2(accS[sl][0][1]); \
    float e2 = ex2(accS[sl][0][2]), e3 = ex2(accS[sl][0][3]); \
    float f0 = ex2(accS[sl][1][0]), f1 = ex2(accS[sl][1][1]); \
    float f2 = ex2(accS[sl][1][2]), f3 = ex2(accS[sl][1][3]); \
    lsum0 += (e0 + e1) + (f0 + f1); \
    lsum1 += (e2 + e3) + (f2 + f3); \
    pa[c][0] = pack_bf16(e0, e1); pa[c][1] = pack_bf16(e2, e3); \
    pa[c][2] = pack_bf16(f0, f1); pa[c][3] = pack_bf16(f2, f3); \
} while (0)

    for (int kt = 0; kt < 64; ++kt) {
        int buf = kt & 1;
        CP_WAIT0();
        __syncthreads();
        if (kt < 63) {
            int nx = kt + 1, nb = buf ^ 1;
            cp16(&Ks[nb][srow][scol],     &K[((size_t)(nx * 64 + srow)) * DH + scol]);
            cp16(&Ks[nb][srow][scol + 8], &K[((size_t)(nx * 64 + srow)) * DH + scol + 8]);
            cp16(&Vt[nb][srow][scol],     &V[(size_t)srow * HWX + nx * 64 + scol]);
            cp16(&Vt[nb][srow][scol + 8], &V[(size_t)srow * HWX + nx * 64 + scol + 8]);
            CP_COMMIT();
        }

        // ---- S = Q K^T, pipelined: frag i+2 in flight while mma-ing frag i.
        unsigned kb[3][4];
        unsigned pa[4][4];
        float accS[2][2][4];
#pragma unroll
        for (int sl = 0; sl < 2; ++sl)
#pragma unroll
            for (int h = 0; h < 2; ++h)
#pragma unroll
                for (int j = 0; j < 4; ++j) accS[sl][h][j] = 0.f;
        LDKF(0);
        LDKF(1);
#pragma unroll
        for (int i = 0; i < 16; ++i) {
            int c = i >> 2, s = i & 3, sl = c & 1;
            if (s == 0 && c >= 1) {
                // exp tile c-1 overlaps tile c's mmas; free its slot for c+1
                int ps = (c - 1) & 1;
                EXPPACK(c - 1, ps);
#pragma unroll
                for (int h = 0; h < 2; ++h)
#pragma unroll
                    for (int j = 0; j < 4; ++j) accS[ps][h][j] = 0.f;
            }
            if (i + 2 < 16) LDKF(i + 2);
            mma_bf16(accS[sl][0], qf[s], kb[i % 3][0], kb[i % 3][1]);
            mma_bf16(accS[sl][1], qf[s], kb[i % 3][2], kb[i % 3][3]);
        }

        // ---- O += P V, pipelined; first V frags in flight before last exp.
        unsigned vb[3][4];
        LDVF(0);
        LDVF(1);
        EXPPACK(3, 1);
#pragma unroll
        for (int i = 0; i < 16; ++i) {
            int s = i >> 2, np = i & 3;
            if (i + 2 < 16) LDVF(i + 2);
            mma_bf16(oacc[np * 2],     pa[s], vb[i % 3][0], vb[i % 3][1]);
            mma_bf16(oacc[np * 2 + 1], pa[s], vb[i % 3][2], vb[i % 3][3]);
        }
    }
#undef LDKF
#undef LDVF
#undef EXPPACK

    lsum0 += __shfl_xor_sync(0xffffffffu, lsum0, 1);
    lsum0 += __shfl_xor_sync(0xffffffffu, lsum0, 2);
    lsum1 += __shfl_xor_sync(0xffffffffu, lsum1, 1);
    lsum1 += __shfl_xor_sync(0xffffffffu, lsum1, 2);
    float inv0 = 1.f / lsum0, inv1 = 1.f / lsum1;

    __nv_bfloat16* Y = g_y + ((size_t)n * NH + hh) * (size_t)HWX * DH;
#pragma unroll
    for (int nt = 0; nt < 8; ++nt) {
        int d0 = nt * 8 + lc * 2;
        *(unsigned*)&Y[(size_t)r0 * DH + d0] =
            pack_bf16(oacc[nt][0] * inv0, oacc[nt][1] * inv0);
        *(unsigned*)&Y[(size_t)(r0 + 8) * DH + d0] =
            pack_bf16(oacc[nt][2] * inv1, oacc[nt][3] * inv1);
    }
}

// ---------------------------------------------------------------------------
// Output projection: bf16 mma + ldmatrix. C[m=o][n=p] = sum_c Wout[o,c] y[c,p].
// ---------------------------------------------------------------------------
__global__ void __launch_bounds__(256) outproj_k(
        const float* __restrict__ x,
        const float* __restrict__ wout,
        const float* __restrict__ bout,
        float* __restrict__ out) {
    int n = blockIdx.z;
    int p0 = blockIdx.x * 64, o0 = blockIdx.y * 128;
    int tid = threadIdx.x, w = tid >> 5, lane = tid & 31;
    int lr = lane >> 2, lc = lane & 3;
    int lmrow = lane & 7, lmmat = lane >> 3;

    __shared__ __nv_bfloat16 As[128][72];  // Wout [o][c]
    __shared__ __nv_bfloat16 Bs[64][72];   // Y [p][d] per head chunk

    float acc[8][4];
#pragma unroll
    for (int i = 0; i < 8; ++i)
#pragma unroll
        for (int j = 0; j < 4; ++j) acc[i][j] = 0.f;

    int ar = tid >> 1, ah = tid & 1;
    int br = tid >> 2, bq = tid & 3;

    for (int hh = 0; hh < 4; ++hh) {
        int c0 = hh * 64;
#pragma unroll
        for (int i = 0; i < 8; ++i) {
            int cc = ah * 32 + i * 4;
            float4 wv = *(const float4*)&wout[(o0 + ar) * CC + c0 + cc];
            As[ar][cc+0] = __float2bfloat16(wv.x);
            As[ar][cc+1] = __float2bfloat16(wv.y);
            As[ar][cc+2] = __float2bfloat16(wv.z);
            As[ar][cc+3] = __float2bfloat16(wv.w);
        }
        {
            const __nv_bfloat16* Yb = g_y + ((size_t)n * NH + hh) * (size_t)HWX * DH;
            const uint4* src = (const uint4*)&Yb[(size_t)(p0 + br) * DH + bq * 16];
            uint4 y0 = src[0], y1 = src[1];
            *(uint4*)&Bs[br][bq * 16]     = y0;
            *(uint4*)&Bs[br][bq * 16 + 8] = y1;
        }
        __syncthreads();
#pragma unroll
        for (int s = 0; s < 4; ++s) {
            int col = s * 16;
            unsigned a[4];
            ldsm4(a[0], a[1], a[2], a[3],
                  &As[w * 16 + (lmmat & 1) * 8 + lmrow][col + (lmmat >> 1) * 8]);
#pragma unroll
            for (int np = 0; np < 4; ++np) {
                unsigned b00, b01, b10, b11;
                ldsm4(b00, b01, b10, b11,
                      &Bs[(np * 2 + (lmmat >> 1)) * 8 + lmrow][col + (lmmat & 1) * 8]);
                mma_bf16(acc[np * 2],     a, b00, b01);
                mma_bf16(acc[np * 2 + 1], a, b10, b11);
            }
        }
        __syncthreads();
    }

    const float* xb = x + (size_t)n * CNT;
    float*       ob = out + (size_t)n * CNT;
    int o_r = o0 + w * 16 + lr;
    float biasA = bout[o_r], biasB = bout[o_r + 8];
#pragma unroll
    for (int nt = 0; nt < 8; ++nt) {
        int p = p0 + nt * 8 + lc * 2;
        float2 xrA = *(const float2*)&xb[(size_t)o_r * HWX + p];
        float2 xrB = *(const float2*)&xb[(size_t)(o_r + 8) * HWX + p];
        float2 rA = make_float2(acc[nt][0] + biasA + xrA.x,
                                acc[nt][1] + biasA + xrA.y);
        float2 rB = make_float2(acc[nt][2] + biasB + xrB.x,
                                acc[nt][3] + biasB + xrB.y);
        *(float2*)&ob[(size_t)o_r * HWX + p]       = rA;
        *(float2*)&ob[(size_t)(o_r + 8) * HWX + p] = rB;
    }
}

// ---------------------------------------------------------------------------
extern "C" void kernel_launch(void* const* d_in, const int* in_sizes, int n_in,
                              void* d_out, int out_size) {
    const float* x     = (const float*)d_in[0];
    const float* gamma = (const float*)d_in[1];
    const float* beta  = (const float*)d_in[2];
    const float* wqkv  = (const float*)d_in[3];
    const float* bqkv  = (const float*)d_in[4];
    const float* wout  = (const float*)d_in[5];
    const float* bout  = (const float*)d_in[6];
    float* out = (float*)d_out;

    gn_partial_k<<<dim3(64, NN), 256>>>(x);
    gn_final_k  <<<NN, 64>>>();
    qkv_gemm_k  <<<dim3(32, 12, NN), 256>>>(x, wqkv, bqkv, gamma, beta);
    attn_k      <<<dim3(32, NH, NN), 256>>>();
    outproj_k   <<<dim3(64, 2, NN), 256>>>(x, wout, bout, out);
}